// round 9
// baseline (speedup 1.0000x reference)
#include <cuda_runtime.h>
#include <cstdint>

typedef unsigned long long u64;

#define NK    64
#define PLANE (256 * 64)
#define CH    (256 * 256 * 64)
#define NSEG  9
#define NBLK  (2 * 16 * NSEG)   // 288

__device__ double g_div_sum;
__device__ double g_smooth_sum;
__device__ float  g_sbin[2][63];
__device__ float  g_qbin[2][63];
__device__ unsigned g_done;

// ---------------- f32x2 packed helpers ----------------
__device__ __forceinline__ u64 F2(float lo, float hi) {
    u64 r; asm("mov.b64 %0,{%1,%2};" : "=l"(r) : "f"(lo), "f"(hi)); return r;
}
__device__ __forceinline__ float F2LO(u64 v) {
    float a, b; asm("mov.b64 {%0,%1},%2;" : "=f"(a), "=f"(b) : "l"(v)); return a;
}
__device__ __forceinline__ float F2HI(u64 v) {
    float a, b; asm("mov.b64 {%0,%1},%2;" : "=f"(a), "=f"(b) : "l"(v)); return b;
}
__device__ __forceinline__ u64 ADD2(u64 a, u64 b) {
    u64 r; asm("add.rn.f32x2 %0,%1,%2;" : "=l"(r) : "l"(a), "l"(b)); return r;
}
__device__ __forceinline__ u64 MUL2(u64 a, u64 b) {
    u64 r; asm("mul.rn.f32x2 %0,%1,%2;" : "=l"(r) : "l"(a), "l"(b)); return r;
}
__device__ __forceinline__ u64 FMA2(u64 a, u64 b, u64 c) {
    u64 r; asm("fma.rn.f32x2 %0,%1,%2,%3;" : "=l"(r) : "l"(a), "l"(b), "l"(c)); return r;
}
// a - b  ==  fma(b, -1, a)
#define KNEG1 0xBF800000BF800000ULL
__device__ __forceinline__ u64 SUB2(u64 a, u64 b) { return FMA2(b, KNEG1, a); }
__device__ __forceinline__ u64 ABS2(u64 a) {
    u64 r; asm("and.b64 %0,%1,0x7FFFFFFF7FFFFFFF;" : "=l"(r) : "l"(a)); return r;
}
__device__ __forceinline__ void pf_l2(const void* p) {
    asm volatile("prefetch.global.L2 [%0];" :: "l"(p));
}

struct RowP {
    u64 bxjL, bxjH, bxpL, bxpH, byjL, byjH, bypL, bypH, szL, szH;
    u64 zjL, zjH, zpL, zpH;
    float zj4, zp4;
};

__global__ void __launch_bounds__(256, 2) kFused(const float* __restrict__ zg,
                                                 const float* __restrict__ tg,
                                                 float* __restrict__ out) {
    const int tid = threadIdx.x;
    const int k4  = tid & 15;
    const int col = tid >> 4;
    const int kk  = 4 * k4;
    const unsigned FM = 0xffffffffu;

    int bid  = blockIdx.x;
    int jt   = bid & 15;
    int rest = bid >> 4;
    int seg  = rest % NSEG;
    int b    = rest / NSEG;
    int i0   = (seg * 256) / NSEG;
    int i1   = ((seg + 1) * 256) / NSEG;

    int j   = jt * 16 + col;
    int jmc = (j > 0)   ? j - 1 : 0;
    int jpc = (j < 255) ? j + 1 : 255;
    bool jdiv = (j < 255);
    bool jsm  = (j >= 1 && j <= 254);
    bool pfl  = ((k4 & 7) == 0);
    bool l15  = (k4 < 15);

    // packed constants (uniform)
    const u64 KSIX   = F2(6.0f, 6.0f);
    const u64 KSIXTH = F2(1.0f / 6.0f, 1.0f / 6.0f);
    const u64 K8TH   = F2(0.125f, 0.125f);
    const u64 KQ     = F2(0.25f, 0.25f);
    const u64 KD64   = F2(0.015625f, 0.015625f);
    const u64 KEPS   = F2(1e-10f, 1e-10f);
    const u64 MSK01  = F2(k4 >= 1 ? 1.0f : 0.0f, 1.0f);
    const u64 MSK23  = F2(l15 ? 1.0f : 0.0f, l15 ? 1.0f : 0.0f);

    const float* zb = zg + (size_t)b * CH + kk;
    const float* xb = tg + (size_t)b * 3 * CH + kk;
    const float* yb = xb + CH;
    const float* wb = yb + CH;
    size_t offj = (size_t)j * NK, offm = (size_t)jmc * NK, offp = (size_t)jpc * NK;

    __shared__ float shS[63], shQ[63];
    for (int t = tid; t < 63; t += 256) { shS[t] = 0.f; shQ[t] = 0.f; }
    __syncthreads();

    RowP R[2];
    R[0].bxjL = R[0].bxjH = R[0].bxpL = R[0].bxpH = 0ULL;
    R[0].byjL = R[0].byjH = R[0].bypL = R[0].bypH = 0ULL;
    R[0].szL = R[0].szH = 0ULL;
    R[0].zjL = R[0].zjH = R[0].zpL = R[0].zpH = 0ULL;
    R[0].zj4 = R[0].zp4 = 0.f;

    u64 d2C2a = 0, d2C2b = 0, d2C1a = 0, d2C1b = 0;
    u64 d2L1a = 0, d2L1b = 0, d2R1a = 0, d2R1b = 0;
    float d2p1 = 0.f, d2n1 = 0.f;
    u64 sSa = 0, sSb = 0, sQa = 0, sQb = 0;
    u64 accLa = 0, accLb = 0;
    float accD = 0.f;

    const int iters = (i1 - i0) + 2;
    int gi = i0 - 1;
    #pragma unroll 1
    for (int it = 0; it < iters; it++, gi++) {
        RowP& P = R[it & 1];
        RowP& C = R[(it & 1) ^ 1];

        int gic = gi < 0 ? 0 : (gi > 255 ? 255 : gi);
        size_t ro = (size_t)gic * PLANE;

        float4 zmf = *(const float4*)(zb + ro + offm);
        float4 zjf = *(const float4*)(zb + ro + offj);
        float4 zpf = *(const float4*)(zb + ro + offp);
        float4 xjf = *(const float4*)(xb + ro + offj);
        float4 xpf = *(const float4*)(xb + ro + offp);
        float4 yjf = *(const float4*)(yb + ro + offj);
        float4 ypf = *(const float4*)(yb + ro + offp);
        float4 wjf = *(const float4*)(wb + ro + offj);
        float4 wpf = *(const float4*)(wb + ro + offp);

        // L2 prefetch two rows ahead, one lane per 128B line
        {
            int gn = gi + 2; gn = gn > 255 ? 255 : (gn < 0 ? 0 : gn);
            size_t rn = (size_t)gn * PLANE;
            if (pfl) {
                pf_l2(zb + rn + offm); pf_l2(zb + rn + offj); pf_l2(zb + rn + offp);
                pf_l2(xb + rn + offj); pf_l2(xb + rn + offp);
                pf_l2(yb + rn + offj); pf_l2(yb + rn + offp);
                pf_l2(wb + rn + offj); pf_l2(wb + rn + offp);
            }
        }

        u64 zmL = F2(zmf.x, zmf.y), zmH = F2(zmf.z, zmf.w);
        C.zjL = F2(zjf.x, zjf.y); C.zjH = F2(zjf.z, zjf.w);
        C.zpL = F2(zpf.x, zpf.y); C.zpH = F2(zpf.z, zpf.w);
        C.bxjL = F2(xjf.x, xjf.y); C.bxjH = F2(xjf.z, xjf.w);
        C.bxpL = F2(xpf.x, xpf.y); C.bxpH = F2(xpf.z, xpf.w);
        C.byjL = F2(yjf.x, yjf.y); C.byjH = F2(yjf.z, yjf.w);
        C.bypL = F2(ypf.x, ypf.y); C.bypH = F2(ypf.z, ypf.w);
        C.szL  = ADD2(F2(wjf.x, wjf.y), F2(wpf.x, wpf.y));
        C.szH  = ADD2(F2(wjf.z, wjf.w), F2(wpf.z, wpf.w));

        float zm4 = __shfl_down_sync(FM, zmf.x, 1, 16);
        C.zj4 = __shfl_down_sync(FM, zjf.x, 1, 16);
        C.zp4 = __shfl_down_sync(FM, zpf.x, 1, 16);

        // dz for current row (3 columns), packed pairs (t0,t1),(t2,t3)
        u64 zjM = F2(F2HI(C.zjL), F2LO(C.zjH));
        u64 zjT = F2(F2HI(C.zjH), C.zj4);
        u64 dzj01 = SUB2(zjM, C.zjL), dzj23 = SUB2(zjT, C.zjH);
        u64 zpM = F2(F2HI(C.zpL), F2LO(C.zpH));
        u64 zpT = F2(F2HI(C.zpH), C.zp4);
        u64 dzp01 = SUB2(zpM, C.zpL), dzp23 = SUB2(zpT, C.zpH);
        u64 zmM = F2(F2HI(zmL), F2LO(zmH));
        u64 zmT = F2(F2HI(zmH), zm4);
        u64 dzm01 = SUB2(zmM, zmL), dzm23 = SUB2(zmT, zmH);

        u64 d2C0a = MUL2(dzj01, dzj01), d2C0b = MUL2(dzj23, dzj23);
        u64 d2L0a = MUL2(dzm01, dzm01), d2L0b = MUL2(dzm23, dzm23);
        u64 d2R0a = MUL2(dzp01, dzp01), d2R0b = MUL2(dzp23, dzp23);

        float d2p0 = __shfl_up_sync(FM, F2HI(d2C0b), 1, 16);
        float d2n0 = __shfl_down_sync(FM, F2LO(d2C0a), 1, 16);

        // std (center column only); lane15 hi-of-b is garbage but never emitted
        if (gi >= i0 && gi < i1) {
            sSa = ADD2(sSa, dzj01); sQa = FMA2(dzj01, dzj01, sQa);
            sSb = ADD2(sSb, dzj23); sQb = FMA2(dzj23, dzj23, sQb);
        }

        // per-plane quantities for the (P, C) row pair, packed L/H
        u64 p0L = ADD2(P.bxjL, P.bxpL), p0H = ADD2(P.bxjH, P.bxpH);
        u64 p1L = ADD2(C.bxjL, C.bxpL), p1H = ADD2(C.bxjH, C.bxpH);
        u64 q0L = ADD2(P.byjL, C.byjL), q0H = ADD2(P.byjH, C.byjH);
        u64 q1L = ADD2(P.bypL, C.bypL), q1H = ADD2(P.bypH, C.bypH);
        u64 slL = ADD2(P.szL, C.szL),   slH = ADD2(P.szH, C.szH);

        u64 A_L = SUB2(P.zjL, C.zjL), A_H = SUB2(P.zjH, C.zjH);
        u64 B_L = SUB2(P.zpL, C.zpL), B_H = SUB2(P.zpH, C.zpH);
        u64 tL = MUL2(P.bxjL, A_L); tL = FMA2(P.bxpL, B_L, tL);
        tL = FMA2(p1L, ADD2(A_L, B_L), tL);
        tL = FMA2(ADD2(ADD2(C.byjL, C.bypL), P.bypL), SUB2(C.zjL, C.zpL), tL);
        tL = FMA2(ADD2(ADD2(P.byjL, P.bypL), C.bypL), SUB2(P.zjL, P.zpL), tL);
        u64 PvL = MUL2(tL, KSIXTH);
        u64 tH = MUL2(P.bxjH, A_H); tH = FMA2(P.bxpH, B_H, tH);
        tH = FMA2(p1H, ADD2(A_H, B_H), tH);
        tH = FMA2(ADD2(ADD2(C.byjH, C.bypH), P.bypH), SUB2(C.zjH, C.zpH), tH);
        tH = FMA2(ADD2(ADD2(P.byjH, P.bypH), C.bypH), SUB2(P.zjH, P.zpH), tH);
        u64 PvH = MUL2(tH, KSIXTH);

        // plane-4 scalars from next lane's plane-0 results
        float p0_4 = __shfl_down_sync(FM, F2LO(p0L), 1, 16);
        float p1_4 = __shfl_down_sync(FM, F2LO(p1L), 1, 16);
        float q0_4 = __shfl_down_sync(FM, F2LO(q0L), 1, 16);
        float q1_4 = __shfl_down_sync(FM, F2LO(q1L), 1, 16);
        float sl_4 = __shfl_down_sync(FM, F2LO(slL), 1, 16);
        float Pv_4 = __shfl_down_sync(FM, F2LO(PvL), 1, 16);

        if (gi - 1 >= i0 && gi - 1 < i1 && gi <= 255 && jdiv) {
            // shifted packs (t1,t2) and (t3,t4)
            u64 p0M = F2(F2HI(p0L), F2LO(p0H)), p0T = F2(F2HI(p0H), p0_4);
            u64 p1M = F2(F2HI(p1L), F2LO(p1H)), p1T = F2(F2HI(p1H), p1_4);
            u64 q0M = F2(F2HI(q0L), F2LO(q0H)), q0T = F2(F2HI(q0H), q0_4);
            u64 q1M = F2(F2HI(q1L), F2LO(q1H)), q1T = F2(F2HI(q1H), q1_4);
            u64 slM = F2(F2HI(slL), F2LO(slH)), slT = F2(F2HI(slH), sl_4);
            u64 PvM = F2(F2HI(PvL), F2LO(PvH)), PvT = F2(F2HI(PvH), Pv_4);

            // P-row |dz| (both columns)
            u64 PzjM = F2(F2HI(P.zjL), F2LO(P.zjH));
            u64 PzjT = F2(F2HI(P.zjH), P.zj4);
            u64 dPj01 = ABS2(SUB2(PzjM, P.zjL)), dPj23 = ABS2(SUB2(PzjT, P.zjH));
            u64 PzpM = F2(F2HI(P.zpL), F2LO(P.zpH));
            u64 PzpT = F2(F2HI(P.zpH), P.zp4);
            u64 dPp01 = ABS2(SUB2(PzpM, P.zpL)), dPp23 = ABS2(SUB2(PzpT, P.zpH));
            u64 aCj01 = ABS2(dzj01), aCj23 = ABS2(dzj23);
            u64 aCp01 = ABS2(dzp01), aCp23 = ABS2(dzp23);

            // cells pair (t=0,1): lo planes = L, hi planes = M
            {
                u64 A1 = MUL2(ADD2(p1L, p1M), ADD2(aCj01, aCp01));
                u64 A2 = MUL2(ADD2(p0L, p0M), ADD2(dPj01, dPp01));
                u64 A3 = MUL2(ADD2(q1L, q1M), ADD2(dPp01, aCp01));
                u64 A4 = MUL2(ADD2(q0L, q0M), ADD2(dPj01, aCj01));
                u64 s  = ADD2(SUB2(A1, A2), SUB2(A3, A4));
                u64 num = FMA2(s, K8TH, FMA2(SUB2(slM, slL), KQ, SUB2(PvM, PvL)));
                u64 sxx = ADD2(ADD2(p0L, p1L), ADD2(p0M, p1M));
                u64 syy = ADD2(ADD2(q0L, q1L), ADD2(q0M, q1M));
                u64 szz = ADD2(slL, slM);
                u64 t2 = MUL2(sxx, sxx); t2 = FMA2(syy, syy, t2); t2 = FMA2(szz, szz, t2);
                u64 den = FMA2(t2, KD64, KEPS);
                u64 n2 = MUL2(num, num);
                accD += __fdividef(F2LO(n2), F2LO(den))
                      + __fdividef(F2HI(n2), F2HI(den));
            }
            // cells pair (t=2,3): lo = H, hi = T; hi element valid only if k4<15
            {
                u64 A1 = MUL2(ADD2(p1H, p1T), ADD2(aCj23, aCp23));
                u64 A2 = MUL2(ADD2(p0H, p0T), ADD2(dPj23, dPp23));
                u64 A3 = MUL2(ADD2(q1H, q1T), ADD2(dPp23, aCp23));
                u64 A4 = MUL2(ADD2(q0H, q0T), ADD2(dPj23, aCj23));
                u64 s  = ADD2(SUB2(A1, A2), SUB2(A3, A4));
                u64 num = FMA2(s, K8TH, FMA2(SUB2(slT, slH), KQ, SUB2(PvT, PvH)));
                u64 sxx = ADD2(ADD2(p0H, p1H), ADD2(p0T, p1T));
                u64 syy = ADD2(ADD2(q0H, q1H), ADD2(q0T, q1T));
                u64 szz = ADD2(slH, slT);
                u64 t2 = MUL2(sxx, sxx); t2 = FMA2(syy, syy, t2); t2 = FMA2(szz, szz, t2);
                u64 den = FMA2(t2, KD64, KEPS);
                u64 n2 = MUL2(num, num);
                accD += __fdividef(F2LO(n2), F2LO(den));
                if (l15) accD += __fdividef(F2HI(n2), F2HI(den));
            }
        }

        // smooth lap at center row ic = gi-1 (uses previous row's d2)
        int ic = gi - 1;
        if (ic >= i0 && ic < i1 && ic >= 1 && ic <= 254 && gi <= 255 && jsm) {
            u64 km01 = F2(d2p1, F2LO(d2C1a));
            u64 kM   = F2(F2HI(d2C1a), F2LO(d2C1b));
            u64 kp23 = F2(F2HI(d2C1b), d2n1);
            u64 s01 = ADD2(ADD2(d2C2a, d2C0a), ADD2(d2L1a, d2R1a));
            s01 = ADD2(s01, ADD2(km01, kM));
            u64 lap01 = SUB2(MUL2(d2C1a, KSIX), s01);
            u64 s23 = ADD2(ADD2(d2C2b, d2C0b), ADD2(d2L1b, d2R1b));
            s23 = ADD2(s23, ADD2(kM, kp23));
            u64 lap23 = SUB2(MUL2(d2C1b, KSIX), s23);
            accLa = FMA2(MUL2(lap01, lap01), MSK01, accLa);
            accLb = FMA2(MUL2(lap23, lap23), MSK23, accLb);
        }

        // rotate history
        d2C2a = d2C1a; d2C2b = d2C1b;
        d2C1a = d2C0a; d2C1b = d2C0b;
        d2L1a = d2L0a; d2L1b = d2L0b;
        d2R1a = d2R0a; d2R1b = d2R0b;
        d2p1 = d2p0; d2n1 = d2n0;
    }

    // std bins: unpack packed partials -> shared -> global
    {
        float s0 = F2LO(sSa), s1 = F2HI(sSa), s2 = F2LO(sSb), s3 = F2HI(sSb);
        float q0v = F2LO(sQa), q1v = F2HI(sQa), q2v = F2LO(sQb), q3v = F2HI(sQb);
        atomicAdd(&shS[kk], s0);     atomicAdd(&shQ[kk], q0v);
        atomicAdd(&shS[kk + 1], s1); atomicAdd(&shQ[kk + 1], q1v);
        atomicAdd(&shS[kk + 2], s2); atomicAdd(&shQ[kk + 2], q2v);
        if (l15) { atomicAdd(&shS[kk + 3], s3); atomicAdd(&shQ[kk + 3], q3v); }
    }
    __syncthreads();
    for (int t = tid; t < 63; t += 256) {
        atomicAdd(&g_sbin[b][t], shS[t]);
        atomicAdd(&g_qbin[b][t], shQ[t]);
    }

    float accL = (F2LO(accLa) + F2HI(accLa)) + (F2LO(accLb) + F2HI(accLb));

    // block reduce accD, accL
    {
        __shared__ float sa[8], sb2[8];
        #pragma unroll
        for (int o = 16; o > 0; o >>= 1) {
            accD += __shfl_down_sync(FM, accD, o);
            accL += __shfl_down_sync(FM, accL, o);
        }
        int w = tid >> 5;
        if ((tid & 31) == 0) { sa[w] = accD; sb2[w] = accL; }
        __syncthreads();
        if (tid == 0) {
            float tD = 0.f, tL2 = 0.f;
            #pragma unroll
            for (int q = 0; q < 8; q++) { tD += sa[q]; tL2 += sb2[q]; }
            atomicAdd(&g_div_sum, (double)tD);
            atomicAdd(&g_smooth_sum, (double)tL2);
        }
    }

    // last-block finalize
    __threadfence();
    __shared__ bool islast;
    if (tid == 0) {
        unsigned v = atomicAdd(&g_done, 1u);
        islast = (v == gridDim.x - 1);
    }
    __syncthreads();
    if (islast) {
        if (tid == 0) g_done = 0;
        float v = 0.f;
        if (tid < 126) {
            float S = ((float*)g_sbin)[tid];
            float Q = ((float*)g_qbin)[tid];
            float var = (Q - S * S * (1.0f / 65536.0f)) * (1.0f / 65535.0f);
            v = sqrtf(fmaxf(var, 0.f));
        }
        __shared__ float sf[8];
        #pragma unroll
        for (int o = 16; o > 0; o >>= 1) v += __shfl_down_sync(FM, v, o);
        if ((tid & 31) == 0) sf[tid >> 5] = v;
        __syncthreads();
        if (tid == 0) {
            float tot = 0.f;
            #pragma unroll
            for (int q = 0; q < 8; q++) tot += sf[q];
            double lstd = (double)(tot / 126.f);
            out[0] = (float)(g_div_sum * (1.0e9 / 8193150.0));
            out[1] = (float)(g_smooth_sum * (10.0 / 7870952.0) + lstd * 100.0);
        }
    }
}

__global__ void kZ_zero() {
    int t = threadIdx.x;
    if (t == 0) { g_div_sum = 0.0; g_smooth_sum = 0.0; g_done = 0u; }
    if (t < 126) { ((float*)g_sbin)[t] = 0.f; ((float*)g_qbin)[t] = 0.f; }
}

extern "C" void kernel_launch(void* const* d_in, const int* in_sizes, int n_in,
                              void* d_out, int out_size) {
    const float* outp = (const float*)d_in[0];
    const float* tgt  = (const float*)d_in[1];
    if (n_in >= 2 && in_sizes[0] > in_sizes[1]) {
        const float* tmp = outp; outp = tgt; tgt = tmp;
    }
    float* out = (float*)d_out;

    kZ_zero<<<1, 128>>>();
    kFused<<<NBLK, 256>>>(outp, tgt, out);
}

// round 10
// speedup vs baseline: 1.4074x; 1.4074x over previous
#include <cuda_runtime.h>
#include <cuda_bf16.h>

#define NK    64
#define PLANE (256 * 64)
#define CH    (256 * 256 * 64)
#define NSEG  9
#define NBLK  (2 * 16 * NSEG)   // 288

__device__ double g_div_sum;
__device__ double g_smooth_sum;
__device__ float  g_sbin[2][63];
__device__ float  g_qbin[2][63];
__device__ unsigned g_done;

__device__ __forceinline__ void pf_l2(const void* p) {
    asm volatile("prefetch.global.L2 [%0];" :: "l"(p));
}

struct Row {
    float bxj[4], bxp[4], byj[4], byp[4], szr[4];
    float zj[5], zp[5];
};

template<bool INT>
__device__ __forceinline__ void step(
    Row& P, Row& C, int gi, int i0, int i1, bool jdiv, bool jsm,
    bool pfl, int kk,
    const float* __restrict__ zb, const float* __restrict__ xb,
    const float* __restrict__ yb, const float* __restrict__ wb,
    size_t offj, size_t offm, size_t offp,
    float d2C2[4], float d2C1[4], float& d2p1, float& d2n1,
    float d2L1[4], float d2R1[4],
    float sS[4], float sQ[4], float& accD, float& accL)
{
    const unsigned FM = 0xffffffffu;
    int gic;
    if (INT) gic = gi;
    else     gic = gi < 0 ? 0 : (gi > 255 ? 255 : gi);
    size_t ro = (size_t)gic * PLANE;

    float4 zmf = *(const float4*)(zb + ro + offm);
    float4 zjf = *(const float4*)(zb + ro + offj);
    float4 zpf = *(const float4*)(zb + ro + offp);
    float4 xjf = *(const float4*)(xb + ro + offj);
    float4 xpf = *(const float4*)(xb + ro + offp);
    float4 yjf = *(const float4*)(yb + ro + offj);
    float4 ypf = *(const float4*)(yb + ro + offp);
    float4 wjf = *(const float4*)(wb + ro + offj);
    float4 wpf = *(const float4*)(wb + ro + offp);

    // L2 prefetch two rows ahead (1 lane per 128B line)
    {
        int gn = gi + 2; gn = gn > 255 ? 255 : (gn < 0 ? 0 : gn);
        size_t rn = (size_t)gn * PLANE;
        if (pfl) {
            pf_l2(zb + rn + offm); pf_l2(zb + rn + offj); pf_l2(zb + rn + offp);
            pf_l2(xb + rn + offj); pf_l2(xb + rn + offp);
            pf_l2(yb + rn + offj); pf_l2(yb + rn + offp);
            pf_l2(wb + rn + offj); pf_l2(wb + rn + offp);
        }
    }

    float zm[5];
    zm[0] = zmf.x; zm[1] = zmf.y; zm[2] = zmf.z; zm[3] = zmf.w;
    C.zj[0] = zjf.x; C.zj[1] = zjf.y; C.zj[2] = zjf.z; C.zj[3] = zjf.w;
    C.zp[0] = zpf.x; C.zp[1] = zpf.y; C.zp[2] = zpf.z; C.zp[3] = zpf.w;
    C.bxj[0] = xjf.x; C.bxj[1] = xjf.y; C.bxj[2] = xjf.z; C.bxj[3] = xjf.w;
    C.bxp[0] = xpf.x; C.bxp[1] = xpf.y; C.bxp[2] = xpf.z; C.bxp[3] = xpf.w;
    C.byj[0] = yjf.x; C.byj[1] = yjf.y; C.byj[2] = yjf.z; C.byj[3] = yjf.w;
    C.byp[0] = ypf.x; C.byp[1] = ypf.y; C.byp[2] = ypf.z; C.byp[3] = ypf.w;
    C.szr[0] = wjf.x + wpf.x; C.szr[1] = wjf.y + wpf.y;
    C.szr[2] = wjf.z + wpf.z; C.szr[3] = wjf.w + wpf.w;

    zm[4]   = __shfl_down_sync(FM, zm[0],   1, 16);
    C.zj[4] = __shfl_down_sync(FM, C.zj[0], 1, 16);
    C.zp[4] = __shfl_down_sync(FM, C.zp[0], 1, 16);

    float d2C0[4], d2L0[4], d2R0[4];
    #pragma unroll
    for (int t = 0; t < 4; t++) {
        float dc = C.zj[t + 1] - C.zj[t]; d2C0[t] = dc * dc;
        float dl = zm[t + 1]   - zm[t];   d2L0[t] = dl * dl;
        float dr = C.zp[t + 1] - C.zp[t]; d2R0[t] = dr * dr;
    }
    float d2p0 = __shfl_up_sync(FM, d2C0[3], 1, 16);
    float d2n0 = __shfl_down_sync(FM, d2C0[0], 1, 16);

    bool ownC = INT ? true : (gi >= i0 && gi < i1);
    if (ownC) {
        #pragma unroll
        for (int t = 0; t < 4; t++) if (kk + t < 63) {
            float d = C.zj[t + 1] - C.zj[t];
            sS[t] += d; sQ[t] += d * d;
        }
    }

    // Per-plane quantities for the row pair (P, C), planes t = 0..3.
    float p0[4], p1[4], q0[4], q1[4], sz[4], Pv[4], sx[4], sy[4];
    #pragma unroll
    for (int t = 0; t < 4; t++) {
        p0[t] = P.bxj[t] + P.bxp[t];
        p1[t] = C.bxj[t] + C.bxp[t];
        q0[t] = P.byj[t] + C.byj[t];
        q1[t] = P.byp[t] + C.byp[t];
        sz[t] = P.szr[t] + C.szr[t];
        float A = P.zj[t] - C.zj[t];
        float B = P.zp[t] - C.zp[t];
        Pv[t] = (P.bxj[t] * A + P.bxp[t] * B + p1[t] * (A + B)
               + (C.byj[t] + C.byp[t] + P.byp[t]) * (C.zj[t] - C.zp[t])
               + (P.byj[t] + P.byp[t] + C.byp[t]) * (P.zj[t] - P.zp[t]))
               * (1.f / 6.f);
        sx[t] = p0[t] + p1[t];
        sy[t] = q0[t] + q1[t];
    }
    float p0_4 = __shfl_down_sync(FM, p0[0], 1, 16);
    float p1_4 = __shfl_down_sync(FM, p1[0], 1, 16);
    float q0_4 = __shfl_down_sync(FM, q0[0], 1, 16);
    float q1_4 = __shfl_down_sync(FM, q1[0], 1, 16);
    float sz_4 = __shfl_down_sync(FM, sz[0], 1, 16);
    float Pv_4 = __shfl_down_sync(FM, Pv[0], 1, 16);
    float sx_4 = p0_4 + p1_4;
    float sy_4 = q0_4 + q1_4;

    bool ownP = INT ? true : (gi - 1 >= i0 && gi - 1 < i1 && gi <= 255);
    if (ownP && jdiv) {
        #pragma unroll
        for (int t = 0; t < 4; t++) if (kk + t < 63) {
            float np0 = (t < 3) ? p0[t + 1] : p0_4;
            float np1 = (t < 3) ? p1[t + 1] : p1_4;
            float nq0 = (t < 3) ? q0[t + 1] : q0_4;
            float nq1 = (t < 3) ? q1[t + 1] : q1_4;
            float nsz = (t < 3) ? sz[t + 1] : sz_4;
            float nPv = (t < 3) ? Pv[t + 1] : Pv_4;
            float nsx = (t < 3) ? sx[t + 1] : sx_4;
            float nsy = (t < 3) ? sy[t + 1] : sy_4;
            float d00 = fabsf(P.zj[t + 1] - P.zj[t]);
            float d01 = fabsf(P.zp[t + 1] - P.zp[t]);
            float d10 = fabsf(C.zj[t + 1] - C.zj[t]);
            float d11 = fabsf(C.zp[t + 1] - C.zp[t]);
            float A1 = (p1[t] + np1) * (d10 + d11);
            float A2 = (p0[t] + np0) * (d00 + d01);
            float A3 = (q1[t] + nq1) * (d01 + d11);
            float A4 = (q0[t] + nq0) * (d00 + d10);
            float num = 0.125f * ((A1 - A2) + (A3 - A4))
                      + 0.25f * (nsz - sz[t]) + (nPv - Pv[t]);
            float sxx = sx[t] + nsx;
            float syy = sy[t] + nsy;
            float szz = sz[t] + nsz;
            float den = 0.015625f * (sxx * sxx + syy * syy + szz * szz) + 1e-10f;
            accD += __fdividef(num * num, den);
        }
    }

    int ic = gi - 1;
    bool smok;
    if (INT) smok = (ic >= 1) && (ic <= 254) && jsm;
    else     smok = (ic >= i0) && (ic < i1) && (ic >= 1) && (ic <= 254)
                    && (gi <= 255) && jsm;
    if (smok) {
        #pragma unroll
        for (int t = 0; t < 4; t++) {
            int k = kk + t;
            if (k >= 1 && k <= 61) {
                float km = (t > 0) ? d2C1[t - 1] : d2p1;
                float kp = (t < 3) ? d2C1[t + 1] : d2n1;
                float lap = 6.f * d2C1[t] - d2C2[t] - d2C0[t]
                          - d2L1[t] - d2R1[t] - km - kp;
                accL += lap * lap;
            }
        }
    }

    #pragma unroll
    for (int t = 0; t < 4; t++) {
        d2C2[t] = d2C1[t]; d2C1[t] = d2C0[t];
        d2L1[t] = d2L0[t]; d2R1[t] = d2R0[t];
    }
    d2p1 = d2p0; d2n1 = d2n0;
}

__global__ void __launch_bounds__(256, 2) kFused(const float* __restrict__ zg,
                                                 const float* __restrict__ tg,
                                                 float* __restrict__ out) {
    const int tid = threadIdx.x;
    const int k4  = tid & 15;
    const int col = tid >> 4;
    const int kk  = 4 * k4;

    int bid  = blockIdx.x;
    int jt   = bid & 15;
    int rest = bid >> 4;
    int seg  = rest % NSEG;
    int b    = rest / NSEG;
    int i0   = (seg * 256) / NSEG;
    int i1   = ((seg + 1) * 256) / NSEG;

    int j   = jt * 16 + col;
    int jmc = (j > 0)   ? j - 1 : 0;
    int jpc = (j < 255) ? j + 1 : 255;
    bool jdiv = (j < 255);
    bool jsm  = (j >= 1 && j <= 254);
    bool pfl  = ((k4 & 7) == 0);

    const float* zb = zg + (size_t)b * CH + kk;
    const float* xb = tg + (size_t)b * 3 * CH + kk;
    const float* yb = xb + CH;
    const float* wb = yb + CH;
    size_t offj = (size_t)j * NK, offm = (size_t)jmc * NK, offp = (size_t)jpc * NK;

    __shared__ float shS[63], shQ[63];
    for (int t = tid; t < 63; t += 256) { shS[t] = 0.f; shQ[t] = 0.f; }
    __syncthreads();

    Row RA, RB;
    #pragma unroll
    for (int t = 0; t < 5; t++) { RA.zj[t] = 0.f; RA.zp[t] = 0.f; }
    #pragma unroll
    for (int t = 0; t < 4; t++) {
        RA.bxj[t] = RA.bxp[t] = RA.byj[t] = RA.byp[t] = RA.szr[t] = 0.f;
    }

    float d2C2[4] = {0,0,0,0}, d2C1[4] = {0,0,0,0};
    float d2L1[4] = {0,0,0,0}, d2R1[4] = {0,0,0,0};
    float d2p1 = 0.f, d2n1 = 0.f;
    float sS[4] = {0,0,0,0}, sQ[4] = {0,0,0,0};
    float accD = 0.f, accL = 0.f;

    // Peel: gi = i0-1, i0 (guarded)
    int gi = i0 - 1;
    step<false>(RA, RB, gi, i0, i1, jdiv, jsm, pfl, kk, zb, xb, yb, wb,
                offj, offm, offp, d2C2, d2C1, d2p1, d2n1, d2L1, d2R1,
                sS, sQ, accD, accL);
    gi++;
    step<false>(RB, RA, gi, i0, i1, jdiv, jsm, pfl, kk, zb, xb, yb, wb,
                offj, offm, offp, d2C2, d2C1, d2p1, d2n1, d2L1, d2R1,
                sS, sQ, accD, accL);
    gi++;

    // Interior: gi in [i0+1, i1-1], unconditional ownership
    #pragma unroll 1
    for (; gi + 1 <= i1 - 1; gi += 2) {
        step<true>(RA, RB, gi, i0, i1, jdiv, jsm, pfl, kk, zb, xb, yb, wb,
                   offj, offm, offp, d2C2, d2C1, d2p1, d2n1, d2L1, d2R1,
                   sS, sQ, accD, accL);
        step<true>(RB, RA, gi + 1, i0, i1, jdiv, jsm, pfl, kk, zb, xb, yb, wb,
                   offj, offm, offp, d2C2, d2C1, d2p1, d2n1, d2L1, d2R1,
                   sS, sQ, accD, accL);
    }
    bool flip = false;
    if (gi <= i1 - 1) {
        step<true>(RA, RB, gi, i0, i1, jdiv, jsm, pfl, kk, zb, xb, yb, wb,
                   offj, offm, offp, d2C2, d2C1, d2p1, d2n1, d2L1, d2R1,
                   sS, sQ, accD, accL);
        gi++;
        flip = true;
    }

    // Final: gi = i1 (guarded)
    if (!flip)
        step<false>(RA, RB, gi, i0, i1, jdiv, jsm, pfl, kk, zb, xb, yb, wb,
                    offj, offm, offp, d2C2, d2C1, d2p1, d2n1, d2L1, d2R1,
                    sS, sQ, accD, accL);
    else
        step<false>(RB, RA, gi, i0, i1, jdiv, jsm, pfl, kk, zb, xb, yb, wb,
                    offj, offm, offp, d2C2, d2C1, d2p1, d2n1, d2L1, d2R1,
                    sS, sQ, accD, accL);

    // std bins: thread partials -> shared -> global
    #pragma unroll
    for (int t = 0; t < 4; t++) if (kk + t < 63) {
        atomicAdd(&shS[kk + t], sS[t]);
        atomicAdd(&shQ[kk + t], sQ[t]);
    }
    __syncthreads();
    for (int t = tid; t < 63; t += 256) {
        atomicAdd(&g_sbin[b][t], shS[t]);
        atomicAdd(&g_qbin[b][t], shQ[t]);
    }

    // block reduce accD, accL
    {
        __shared__ float sa[8], sb2[8];
        const unsigned FM = 0xffffffffu;
        #pragma unroll
        for (int o = 16; o > 0; o >>= 1) {
            accD += __shfl_down_sync(FM, accD, o);
            accL += __shfl_down_sync(FM, accL, o);
        }
        int w = tid >> 5;
        if ((tid & 31) == 0) { sa[w] = accD; sb2[w] = accL; }
        __syncthreads();
        if (tid == 0) {
            float tD = 0.f, tL = 0.f;
            #pragma unroll
            for (int q = 0; q < 8; q++) { tD += sa[q]; tL += sb2[q]; }
            atomicAdd(&g_div_sum, (double)tD);
            atomicAdd(&g_smooth_sum, (double)tL);
        }
    }

    // last-block finalize
    __threadfence();
    __shared__ bool islast;
    if (tid == 0) {
        unsigned v = atomicAdd(&g_done, 1u);
        islast = (v == gridDim.x - 1);
    }
    __syncthreads();
    if (islast) {
        if (tid == 0) g_done = 0;
        float v = 0.f;
        if (tid < 126) {
            float S = ((float*)g_sbin)[tid];
            float Q = ((float*)g_qbin)[tid];
            float var = (Q - S * S * (1.0f / 65536.0f)) * (1.0f / 65535.0f);
            v = sqrtf(fmaxf(var, 0.f));
        }
        __shared__ float sf[8];
        const unsigned FM = 0xffffffffu;
        #pragma unroll
        for (int o = 16; o > 0; o >>= 1) v += __shfl_down_sync(FM, v, o);
        if ((tid & 31) == 0) sf[tid >> 5] = v;
        __syncthreads();
        if (tid == 0) {
            float tot = 0.f;
            #pragma unroll
            for (int q = 0; q < 8; q++) tot += sf[q];
            double lstd = (double)(tot / 126.f);
            out[0] = (float)(g_div_sum * (1.0e9 / 8193150.0));
            out[1] = (float)(g_smooth_sum * (10.0 / 7870952.0) + lstd * 100.0);
        }
    }
}

__global__ void kZ_zero() {
    int t = threadIdx.x;
    if (t == 0) { g_div_sum = 0.0; g_smooth_sum = 0.0; g_done = 0u; }
    if (t < 126) { ((float*)g_sbin)[t] = 0.f; ((float*)g_qbin)[t] = 0.f; }
}

extern "C" void kernel_launch(void* const* d_in, const int* in_sizes, int n_in,
                              void* d_out, int out_size) {
    const float* outp = (const float*)d_in[0];
    const float* tgt  = (const float*)d_in[1];
    if (n_in >= 2 && in_sizes[0] > in_sizes[1]) {
        const float* tmp = outp; outp = tgt; tgt = tmp;
    }
    float* out = (float*)d_out;

    kZ_zero<<<1, 128>>>();
    kFused<<<NBLK, 256>>>(outp, tgt, out);
}